// round 15
// baseline (speedup 1.0000x reference)
#include <cuda_runtime.h>
#include <cuda_fp16.h>
#include <math.h>
#include <cstdint>

// Problem shape (fixed)
#define Bb    4
#define Ss    4096
#define Dd    1024
#define Mtot  (Bb * Ss)        // 16384 rows
#define MD    ((size_t)Mtot * Dd)
#define CHUNKS 128
#define TT     32              // Ss / CHUNKS
#define NCH   (Bb * Dd)

// GEMM tiling: CTA 128x256, 8 warps (2x4), warp tile 64x64
#define TBM 128
#define TBN 256
#define KC  64                 // K chunk: 64 fp16 = 128B rows (SW128 swizzle)
#define NKC (Dd / KC)          // 16
#define STAGES 3
#define A_BYTES 16384          // 128 rows x 128B
#define B_BYTES 32768          // 256 rows x 128B
#define STAGE_BYTES (A_BYTES + B_BYTES)     // 48KB
#define OFF_A 0
#define OFF_B A_BYTES
#define SMEM_TOTAL (STAGES * STAGE_BYTES)   // 147456

// Scratch (__device__ globals; no allocation allowed)
__device__ __half g_lin_h[3ll * Mtot * Dd];  // fp16 GEMM outputs g,v,d
__device__ __half g_xh[Mtot * Dd];           // x fp16; REUSED as cumprod P after GEMM
__device__ __half g_wh[3 * Dd * Dd];
__device__ float g_carry[CHUNKS * NCH];      // carry entering each chunk

// ---------------- helpers ----------------
__device__ __forceinline__ uint32_t smem_u32(const void* p) {
    uint32_t a;
    asm("{ .reg .u64 t; cvta.to.shared.u64 t, %1; cvt.u32.u64 %0, t; }" : "=r"(a) : "l"(p));
    return a;
}
__device__ __forceinline__ void cp_async16(uint32_t s, const void* g) {
    asm volatile("{ .reg .u64 ga; cvta.to.global.u64 ga, %1; "
                 "cp.async.cg.shared.global [%0], [ga], 16; }"
                 :: "r"(s), "l"(g) : "memory");
}
#define CP_COMMIT() asm volatile("cp.async.commit_group;" ::: "memory")

#define LDSM4(r, addr) \
    asm volatile("ldmatrix.sync.aligned.m8n8.x4.shared.b16 {%0,%1,%2,%3}, [%4];" \
        : "=r"((r)[0]), "=r"((r)[1]), "=r"((r)[2]), "=r"((r)[3]) : "r"(addr))

__device__ __forceinline__ void mma_f16(float* c, const uint32_t* a,
                                        uint32_t b0, uint32_t b1) {
    asm volatile("mma.sync.aligned.m16n8k16.row.col.f32.f16.f16.f32 "
        "{%0,%1,%2,%3}, {%4,%5,%6,%7}, {%8,%9}, {%0,%1,%2,%3};"
        : "+f"(c[0]), "+f"(c[1]), "+f"(c[2]), "+f"(c[3])
        : "r"(a[0]), "r"(a[1]), "r"(a[2]), "r"(a[3]), "r"(b0), "r"(b1));
}

// fast gate math: MUFU-only (EX2 + RCP), no fp32 division
__device__ __forceinline__ float sigmoidf_(float x) {
    return __fdividef(1.0f, 1.0f + __expf(-x));
}
__device__ __forceinline__ float tanhf_(float v) {
    return 1.0f - __fdividef(2.0f, __expf(2.0f * v) + 1.0f);
}

// ---------------------------------------------------------------------------
// fp32 -> fp16 conversions
// ---------------------------------------------------------------------------
__global__ __launch_bounds__(256)
void convert_x_kernel(const float* __restrict__ x) {
    int i = blockIdx.x * blockDim.x + threadIdx.x;   // float4 index
    float4 v = ((const float4*)x)[i];
    ((__half2*)g_xh)[2 * i]     = __floats2half2_rn(v.x, v.y);
    ((__half2*)g_xh)[2 * i + 1] = __floats2half2_rn(v.z, v.w);
}

__global__ __launch_bounds__(256)
void convert_w_kernel(const float* __restrict__ Wg, const float* __restrict__ Wv,
                      const float* __restrict__ Wd) {
    int i = blockIdx.x * blockDim.x + threadIdx.x;
    const int per = Dd * Dd / 4;
    int mat = i / per, rem = i - mat * per;
    const float* src = (mat == 0) ? Wg : (mat == 1) ? Wv : Wd;
    float4 v = ((const float4*)src)[rem];
    ((__half2*)g_wh)[2 * i]     = __floats2half2_rn(v.x, v.y);
    ((__half2*)g_wh)[2 * i + 1] = __floats2half2_rn(v.z, v.w);
}

// ---------------------------------------------------------------------------
// Stage loader: A tile 128 rows + B tile 256 rows, 128B rows, SW128 swizzle.
// 12 x cp.async(16B) per thread.
// ---------------------------------------------------------------------------
__device__ __forceinline__ void issue_stage(uint32_t sbase, int s,
    const __half* a, const __half* b, int kc, int tid)
{
    uint32_t base = sbase + s * STAGE_BYTES;
    const __half* asrc = a + kc * KC;
    #pragma unroll
    for (int it = 0; it < 4; it++) {          // A: 1024 units
        int u = tid + it * 256;
        int r = u >> 3, seg = u & 7;
        uint32_t dst = base + OFF_A + r * 128 + ((uint32_t)(seg ^ (r & 7)) << 4);
        cp_async16(dst, asrc + (size_t)r * Dd + seg * 8);
    }
    const __half* bsrc = b + kc * KC;
    #pragma unroll
    for (int it = 0; it < 8; it++) {          // B: 2048 units
        int u = tid + it * 256;
        int r = u >> 3, seg = u & 7;
        uint32_t dst = base + OFF_B + r * 128 + ((uint32_t)(seg ^ (r & 7)) << 4);
        cp_async16(dst, bsrc + (size_t)r * Dd + seg * 8);
    }
}

// ---------------------------------------------------------------------------
// fp16 mma.sync GEMM: C[m,n] = sum_k A[m,k]*W[n,k]  (one of g/v/d per z)
// CTA 128x256, 8 warps (2x4), warp tile 64x64, 3-stage cp.async pipeline.
// ---------------------------------------------------------------------------
__global__ __launch_bounds__(256)
void gemm_mma_kernel()
{
    extern __shared__ char smem[];
    const uint32_t sbase = smem_u32(smem);
    const int tid = threadIdx.x, lane = tid & 31, wid = tid >> 5;
    const int wm = wid >> 2, wn = wid & 3;
    const int m0 = blockIdx.y * TBM, n0 = blockIdx.x * TBN, mat = blockIdx.z;

    const __half* a_src = g_xh + (size_t)m0 * Dd;
    const __half* b_src = g_wh + ((size_t)mat * Dd + n0) * Dd;

    issue_stage(sbase, 0, a_src, b_src, 0, tid); CP_COMMIT();
    issue_stage(sbase, 1, a_src, b_src, 1, tid); CP_COMMIT();

    float acc[4][8][4] = {};   // 128 accumulators: 4 m16 x 8 n8

    // per-lane ldmatrix addressing (row stride 128B, SW128)
    const int r8 = lane & 7, q = lane >> 3;
    const int a_row_loc = (q & 1) * 8 + r8;
    const int a_seg_add = q >> 1;            // k16 half
    const int b_row_loc = (q >> 1) * 8 + r8;
    const int b_seg_add = q & 1;
    const uint32_t a_off0 = (uint32_t)(wm * 64 + a_row_loc) * 128;
    const uint32_t b_off0 = (uint32_t)(wn * 64 + b_row_loc) * 128;

    for (int kc = 0; kc < NKC; kc++) {
        if (kc + 2 < NKC) {
            issue_stage(sbase, (kc + 2) % STAGES, a_src, b_src, kc + 2, tid);
            CP_COMMIT();
            asm volatile("cp.async.wait_group 2;" ::: "memory");
        } else if (kc + 1 < NKC) {
            asm volatile("cp.async.wait_group 1;" ::: "memory");
        } else {
            asm volatile("cp.async.wait_group 0;" ::: "memory");
        }
        __syncthreads();

        const uint32_t st = sbase + (kc % STAGES) * STAGE_BYTES;
        #pragma unroll
        for (int ks = 0; ks < 4; ks++) {          // 4 x k16 steps within KC=64
            uint32_t af[4][4];
            #pragma unroll
            for (int mi = 0; mi < 4; mi++) {
                uint32_t off = a_off0 + mi * (16 * 128)
                             + ((uint32_t)((ks * 2 + a_seg_add) ^ r8) << 4);
                LDSM4(af[mi], st + OFF_A + off);
            }
            uint32_t bf[4][4];
            #pragma unroll
            for (int j = 0; j < 4; j++) {         // 4 x 16-col groups = 64 cols
                uint32_t off = b_off0 + j * (16 * 128)
                             + ((uint32_t)((ks * 2 + b_seg_add) ^ r8) << 4);
                LDSM4(bf[j], st + OFF_B + off);
            }
            #pragma unroll
            for (int mi = 0; mi < 4; mi++) {
                #pragma unroll
                for (int ni = 0; ni < 8; ni++) {
                    const int j = ni >> 1, sub = ni & 1;
                    mma_f16(acc[mi][ni], af[mi], bf[j][sub*2], bf[j][sub*2+1]);
                }
            }
        }
        __syncthreads();
    }

    // epilogue: write fp16 GEMM result
    __half* C = g_lin_h + (size_t)mat * MD;
    const int row_base = m0 + wm * 64 + (lane >> 2);
    const int col_base = n0 + wn * 64 + (lane & 3) * 2;
    #pragma unroll
    for (int mi = 0; mi < 4; mi++) {
        const int row = row_base + mi * 16;
        #pragma unroll
        for (int ni = 0; ni < 8; ni++) {
            const int col = col_base + ni * 8;
            *(__half2*)&C[(size_t)row * Dd + col] =
                __floats2half2_rn(acc[mi][ni][0], acc[mi][ni][1]);
            *(__half2*)&C[(size_t)(row + 8) * Dd + col] =
                __floats2half2_rn(acc[mi][ni][2], acc[mi][ni][3]);
        }
    }
}

// ---------------------------------------------------------------------------
// Fused gate + scan pass 1: read fp16 g/v/d, compute gates ONCE, local scan.
// Writes L into out (fp32) and cumprod P into g_xh (fp16, buffer reuse).
// ---------------------------------------------------------------------------
__global__ __launch_bounds__(256)
void scan_gate_kernel(float* __restrict__ out,
                      const float* __restrict__ bg, const float* __restrict__ bv,
                      const float* __restrict__ bd)
{
    int gid = blockIdx.x * blockDim.x + threadIdx.x;
    int d    = gid & (Dd - 1);
    int rest = gid >> 10;
    int b    = rest & (Bb - 1);
    int c    = rest >> 2;

    const float bgd = bg[d], bvd = bv[d], bdd = bd[d];
    size_t base = ((size_t)b * Ss + c * TT) * Dd + d;
    float h = 0.0f, p = 1.0f;
    #pragma unroll 8
    for (int t = 0; t < TT; t++) {
        size_t idx = base + (size_t)t * Dd;
        float gg = __half2float(g_lin_h[idx])          + bgd;
        float vv = __half2float(g_lin_h[idx + MD])     + bvd;
        float dd = __half2float(g_lin_h[idx + 2 * MD]) + bdd;
        float xs = sigmoidf_(gg) * tanhf_(vv);
        float a  = 0.001f + 0.998f * sigmoidf_(dd);
        h = fmaf(a, h, xs);
        p = p * a;
        out[idx]  = h;
        g_xh[idx] = __float2half(p);
    }
}

// ---------------------------------------------------------------------------
// Scan pass 2: per-channel scan over chunk summaries (last elements) -> carries.
// ---------------------------------------------------------------------------
__global__ __launch_bounds__(256)
void scan_carry_kernel(const float* __restrict__ out)
{
    int ch = blockIdx.x * blockDim.x + threadIdx.x;  // 0..NCH-1
    int d = ch & (Dd - 1);
    int b = ch >> 10;

    float cur = 0.0f;
    g_carry[ch] = 0.0f;
    #pragma unroll 8
    for (int c = 0; c < CHUNKS; c++) {
        size_t idx = ((size_t)b * Ss + c * TT + TT - 1) * Dd + d;
        float P = __half2float(g_xh[idx]);
        float L = out[idx];
        cur = fmaf(P, cur, L);
        if (c + 1 < CHUNKS) g_carry[(c + 1) * NCH + ch] = cur;
    }
}

// ---------------------------------------------------------------------------
// Scan pass 3: fixup  out_t += carry[chunk] * P_t  (chunks >= 1)
// ---------------------------------------------------------------------------
__global__ __launch_bounds__(256)
void scan_fix_kernel(float* __restrict__ out)
{
    int e4  = blockIdx.x * blockDim.x + threadIdx.x;
    size_t idx = (size_t)e4 * 4;
    int m = (int)(idx >> 10);
    int s = m & (Ss - 1);
    int c = s >> 5;              // s / TT (TT=32)
    if (c == 0) return;
    int b = m >> 12;
    int d = (int)(idx & (Dd - 1));

    __half2 p01 = *(const __half2*)&g_xh[idx];
    __half2 p23 = *(const __half2*)&g_xh[idx + 2];
    float2 P0 = __half22float2(p01);
    float2 P1 = __half22float2(p23);
    float4 L  = *(float4*)&out[idx];
    float4 cr = *(const float4*)&g_carry[c * NCH + b * Dd + d];
    L.x = fmaf(cr.x, P0.x, L.x);
    L.y = fmaf(cr.y, P0.y, L.y);
    L.z = fmaf(cr.z, P1.x, L.z);
    L.w = fmaf(cr.w, P1.y, L.w);
    *(float4*)&out[idx] = L;
}

// ---------------------------------------------------------------------------
extern "C" void kernel_launch(void* const* d_in, const int* in_sizes, int n_in,
                              void* d_out, int out_size)
{
    const float* x  = (const float*)d_in[0];
    const float* Wg = (const float*)d_in[1];
    const float* bg = (const float*)d_in[2];
    const float* Wv = (const float*)d_in[3];
    const float* bv = (const float*)d_in[4];
    const float* Wd = (const float*)d_in[5];
    const float* bd = (const float*)d_in[6];
    float* out = (float*)d_out;

    cudaFuncSetAttribute(gemm_mma_kernel,
                         cudaFuncAttributeMaxDynamicSharedMemorySize, SMEM_TOTAL);

    convert_x_kernel<<<Mtot * Dd / 4 / 256, 256>>>(x);
    convert_w_kernel<<<3 * Dd * Dd / 4 / 256, 256>>>(Wg, Wv, Wd);

    dim3 grid(Dd / TBN, Mtot / TBM, 3);   // (4, 128, 3)
    gemm_mma_kernel<<<grid, 256, SMEM_TOTAL>>>();

    scan_gate_kernel <<<(NCH * CHUNKS) / 256, 256>>>(out, bg, bv, bd);
    scan_carry_kernel<<<NCH / 256, 256>>>(out);
    scan_fix_kernel  <<<(Mtot * Dd / 4) / 256, 256>>>(out);
}

// round 17
// speedup vs baseline: 1.1603x; 1.1603x over previous
#include <cuda_runtime.h>
#include <cuda_fp16.h>
#include <math.h>
#include <cstdint>

// Problem shape (fixed)
#define Bb    4
#define Ss    4096
#define Dd    1024
#define Mtot  (Bb * Ss)        // 16384 rows
#define MD    ((size_t)Mtot * Dd)
#define CHUNKS 128
#define TT     32              // Ss / CHUNKS
#define NCH   (Bb * Dd)

// GEMM tiling: CTA 128x128, 4 warps (2x2), warp tile 64x64, 128 threads
#define TBM 128
#define TBN 128
#define KC  64                 // K chunk: 64 fp16 = 128B rows (SW128 swizzle)
#define NKC (Dd / KC)          // 16
#define STAGES 3
#define A_BYTES 16384          // 128 rows x 128B
#define B_BYTES 16384
#define STAGE_BYTES (A_BYTES + B_BYTES)     // 32KB
#define OFF_A 0
#define OFF_B A_BYTES
#define SMEM_TOTAL (STAGES * STAGE_BYTES)   // 98304 -> 2 CTAs/SM

// Scratch (__device__ globals; no allocation allowed)
__device__ __half g_lin_h[3ll * Mtot * Dd];  // fp16 GEMM outputs g,v,d
__device__ __half g_xh[Mtot * Dd];           // x fp16; REUSED as cumprod P after GEMM
__device__ __half g_wh[3 * Dd * Dd];
__device__ float g_carry[CHUNKS * NCH];      // carry entering each chunk

// ---------------- helpers ----------------
__device__ __forceinline__ uint32_t smem_u32(const void* p) {
    uint32_t a;
    asm("{ .reg .u64 t; cvta.to.shared.u64 t, %1; cvt.u32.u64 %0, t; }" : "=r"(a) : "l"(p));
    return a;
}
__device__ __forceinline__ void cp_async16(uint32_t s, const void* g) {
    asm volatile("{ .reg .u64 ga; cvta.to.global.u64 ga, %1; "
                 "cp.async.cg.shared.global [%0], [ga], 16; }"
                 :: "r"(s), "l"(g) : "memory");
}
#define CP_COMMIT() asm volatile("cp.async.commit_group;" ::: "memory")

#define LDSM4(r, addr) \
    asm volatile("ldmatrix.sync.aligned.m8n8.x4.shared.b16 {%0,%1,%2,%3}, [%4];" \
        : "=r"((r)[0]), "=r"((r)[1]), "=r"((r)[2]), "=r"((r)[3]) : "r"(addr))

__device__ __forceinline__ void mma_f16(float* c, const uint32_t* a,
                                        uint32_t b0, uint32_t b1) {
    asm volatile("mma.sync.aligned.m16n8k16.row.col.f32.f16.f16.f32 "
        "{%0,%1,%2,%3}, {%4,%5,%6,%7}, {%8,%9}, {%0,%1,%2,%3};"
        : "+f"(c[0]), "+f"(c[1]), "+f"(c[2]), "+f"(c[3])
        : "r"(a[0]), "r"(a[1]), "r"(a[2]), "r"(a[3]), "r"(b0), "r"(b1));
}

// fast gate math: MUFU-only (EX2 + RCP), no fp32 division
__device__ __forceinline__ float sigmoidf_(float x) {
    return __fdividef(1.0f, 1.0f + __expf(-x));
}
__device__ __forceinline__ float tanhf_(float v) {
    return 1.0f - __fdividef(2.0f, __expf(2.0f * v) + 1.0f);
}

// ---------------------------------------------------------------------------
// fp32 -> fp16 conversions
// ---------------------------------------------------------------------------
__global__ __launch_bounds__(256)
void convert_x_kernel(const float* __restrict__ x) {
    int i = blockIdx.x * blockDim.x + threadIdx.x;   // float4 index
    float4 v = ((const float4*)x)[i];
    ((__half2*)g_xh)[2 * i]     = __floats2half2_rn(v.x, v.y);
    ((__half2*)g_xh)[2 * i + 1] = __floats2half2_rn(v.z, v.w);
}

__global__ __launch_bounds__(256)
void convert_w_kernel(const float* __restrict__ Wg, const float* __restrict__ Wv,
                      const float* __restrict__ Wd) {
    int i = blockIdx.x * blockDim.x + threadIdx.x;
    const int per = Dd * Dd / 4;
    int mat = i / per, rem = i - mat * per;
    const float* src = (mat == 0) ? Wg : (mat == 1) ? Wv : Wd;
    float4 v = ((const float4*)src)[rem];
    ((__half2*)g_wh)[2 * i]     = __floats2half2_rn(v.x, v.y);
    ((__half2*)g_wh)[2 * i + 1] = __floats2half2_rn(v.z, v.w);
}

// ---------------------------------------------------------------------------
// Stage loader: A + B tiles, 128 rows x 128B each, SW128 swizzle.
// 128 threads -> 16 cp.async(16B) per thread.
// ---------------------------------------------------------------------------
__device__ __forceinline__ void issue_stage(uint32_t sbase, int s,
    const __half* a, const __half* b, int kc, int tid)
{
    uint32_t base = sbase + s * STAGE_BYTES;
    const __half* asrc = a + kc * KC;
    #pragma unroll
    for (int it = 0; it < 8; it++) {          // A: 1024 16B units
        int u = tid + it * 128;
        int r = u >> 3, seg = u & 7;
        uint32_t dst = base + OFF_A + r * 128 + ((uint32_t)(seg ^ (r & 7)) << 4);
        cp_async16(dst, asrc + (size_t)r * Dd + seg * 8);
    }
    const __half* bsrc = b + kc * KC;
    #pragma unroll
    for (int it = 0; it < 8; it++) {          // B: 1024 16B units
        int u = tid + it * 128;
        int r = u >> 3, seg = u & 7;
        uint32_t dst = base + OFF_B + r * 128 + ((uint32_t)(seg ^ (r & 7)) << 4);
        cp_async16(dst, bsrc + (size_t)r * Dd + seg * 8);
    }
}

// ---------------------------------------------------------------------------
// fp16 mma.sync GEMM: C[m,n] = sum_k A[m,k]*W[n,k]  (one of g/v/d per z)
// CTA 128x128, 4 warps (2x2), warp tile 64x64, 3-stage pipeline, 2 CTAs/SM.
// ---------------------------------------------------------------------------
__global__ __launch_bounds__(128, 2)
void gemm_mma_kernel()
{
    extern __shared__ char smem[];
    const uint32_t sbase = smem_u32(smem);
    const int tid = threadIdx.x, lane = tid & 31, wid = tid >> 5;
    const int wm = wid >> 1, wn = wid & 1;
    const int m0 = blockIdx.y * TBM, n0 = blockIdx.x * TBN, mat = blockIdx.z;

    const __half* a_src = g_xh + (size_t)m0 * Dd;
    const __half* b_src = g_wh + ((size_t)mat * Dd + n0) * Dd;

    issue_stage(sbase, 0, a_src, b_src, 0, tid); CP_COMMIT();
    issue_stage(sbase, 1, a_src, b_src, 1, tid); CP_COMMIT();

    float acc[4][8][4] = {};   // 128 accumulators: 4 m16 x 8 n8

    // per-lane ldmatrix addressing (row stride 128B, SW128)
    const int r8 = lane & 7, q = lane >> 3;
    const int a_row_loc = (q & 1) * 8 + r8;
    const int a_seg_add = q >> 1;            // k16 half
    const int b_row_loc = (q >> 1) * 8 + r8;
    const int b_seg_add = q & 1;
    const uint32_t a_off0 = (uint32_t)(wm * 64 + a_row_loc) * 128;
    const uint32_t b_off0 = (uint32_t)(wn * 64 + b_row_loc) * 128;

    for (int kc = 0; kc < NKC; kc++) {
        if (kc + 2 < NKC) {
            issue_stage(sbase, (kc + 2) % STAGES, a_src, b_src, kc + 2, tid);
            CP_COMMIT();
            asm volatile("cp.async.wait_group 2;" ::: "memory");
        } else if (kc + 1 < NKC) {
            asm volatile("cp.async.wait_group 1;" ::: "memory");
        } else {
            asm volatile("cp.async.wait_group 0;" ::: "memory");
        }
        __syncthreads();

        const uint32_t st = sbase + (kc % STAGES) * STAGE_BYTES;
        #pragma unroll
        for (int ks = 0; ks < 4; ks++) {          // 4 x k16 steps within KC=64
            uint32_t af[4][4];
            #pragma unroll
            for (int mi = 0; mi < 4; mi++) {
                uint32_t off = a_off0 + mi * (16 * 128)
                             + ((uint32_t)((ks * 2 + a_seg_add) ^ r8) << 4);
                LDSM4(af[mi], st + OFF_A + off);
            }
            uint32_t bf[4][4];
            #pragma unroll
            for (int j = 0; j < 4; j++) {         // 4 x 16-col groups = 64 cols
                uint32_t off = b_off0 + j * (16 * 128)
                             + ((uint32_t)((ks * 2 + b_seg_add) ^ r8) << 4);
                LDSM4(bf[j], st + OFF_B + off);
            }
            #pragma unroll
            for (int mi = 0; mi < 4; mi++) {
                #pragma unroll
                for (int ni = 0; ni < 8; ni++) {
                    const int j = ni >> 1, sub = ni & 1;
                    mma_f16(acc[mi][ni], af[mi], bf[j][sub*2], bf[j][sub*2+1]);
                }
            }
        }
        __syncthreads();
    }

    // epilogue: write fp16 GEMM result
    __half* C = g_lin_h + (size_t)mat * MD;
    const int row_base = m0 + wm * 64 + (lane >> 2);
    const int col_base = n0 + wn * 64 + (lane & 3) * 2;
    #pragma unroll
    for (int mi = 0; mi < 4; mi++) {
        const int row = row_base + mi * 16;
        #pragma unroll
        for (int ni = 0; ni < 8; ni++) {
            const int col = col_base + ni * 8;
            *(__half2*)&C[(size_t)row * Dd + col] =
                __floats2half2_rn(acc[mi][ni][0], acc[mi][ni][1]);
            *(__half2*)&C[(size_t)(row + 8) * Dd + col] =
                __floats2half2_rn(acc[mi][ni][2], acc[mi][ni][3]);
        }
    }
}

// ---------------------------------------------------------------------------
// Fused gate + scan pass 1: 2 channels per thread via __half2 loads.
// Writes L into out (fp32) and cumprod P into g_xh (fp16, buffer reuse).
// ---------------------------------------------------------------------------
__global__ __launch_bounds__(256)
void scan_gate_kernel(float* __restrict__ out,
                      const float* __restrict__ bg, const float* __restrict__ bv,
                      const float* __restrict__ bd)
{
    int gid = blockIdx.x * blockDim.x + threadIdx.x;   // (c, b, dpair)
    int dp   = gid & (Dd / 2 - 1);        // 0..511
    int rest = gid >> 9;
    int b    = rest & (Bb - 1);
    int c    = rest >> 2;
    int d    = dp * 2;

    const float2 BG = *(const float2*)&bg[d];
    const float2 BV = *(const float2*)&bv[d];
    const float2 BD = *(const float2*)&bd[d];

    size_t base = ((size_t)b * Ss + c * TT) * Dd + d;
    float h0 = 0.0f, h1 = 0.0f, p0 = 1.0f, p1 = 1.0f;
    #pragma unroll 8
    for (int t = 0; t < TT; t++) {
        size_t idx = base + (size_t)t * Dd;
        float2 G = __half22float2(*(const __half2*)&g_lin_h[idx]);
        float2 V = __half22float2(*(const __half2*)&g_lin_h[idx + MD]);
        float2 D = __half22float2(*(const __half2*)&g_lin_h[idx + 2 * MD]);
        float xs0 = sigmoidf_(G.x + BG.x) * tanhf_(V.x + BV.x);
        float xs1 = sigmoidf_(G.y + BG.y) * tanhf_(V.y + BV.y);
        float a0  = 0.001f + 0.998f * sigmoidf_(D.x + BD.x);
        float a1  = 0.001f + 0.998f * sigmoidf_(D.y + BD.y);
        h0 = fmaf(a0, h0, xs0);
        h1 = fmaf(a1, h1, xs1);
        p0 *= a0;
        p1 *= a1;
        *(float2*)&out[idx] = make_float2(h0, h1);
        *(__half2*)&g_xh[idx] = __floats2half2_rn(p0, p1);
    }
}

// ---------------------------------------------------------------------------
// Scan pass 2: per-channel scan over chunk summaries (last elements) -> carries.
// ---------------------------------------------------------------------------
__global__ __launch_bounds__(256)
void scan_carry_kernel(const float* __restrict__ out)
{
    int ch = blockIdx.x * blockDim.x + threadIdx.x;  // 0..NCH-1
    int d = ch & (Dd - 1);
    int b = ch >> 10;

    float cur = 0.0f;
    g_carry[ch] = 0.0f;
    #pragma unroll 8
    for (int c = 0; c < CHUNKS; c++) {
        size_t idx = ((size_t)b * Ss + c * TT + TT - 1) * Dd + d;
        float P = __half2float(g_xh[idx]);
        float L = out[idx];
        cur = fmaf(P, cur, L);
        if (c + 1 < CHUNKS) g_carry[(c + 1) * NCH + ch] = cur;
    }
}

// ---------------------------------------------------------------------------
// Scan pass 3: fixup  out_t += carry[chunk] * P_t  (chunks >= 1)
// ---------------------------------------------------------------------------
__global__ __launch_bounds__(256)
void scan_fix_kernel(float* __restrict__ out)
{
    int e4  = blockIdx.x * blockDim.x + threadIdx.x;
    size_t idx = (size_t)e4 * 4;
    int m = (int)(idx >> 10);
    int s = m & (Ss - 1);
    int c = s >> 5;              // s / TT (TT=32)
    if (c == 0) return;
    int b = m >> 12;
    int d = (int)(idx & (Dd - 1));

    __half2 p01 = *(const __half2*)&g_xh[idx];
    __half2 p23 = *(const __half2*)&g_xh[idx + 2];
    float2 P0 = __half22float2(p01);
    float2 P1 = __half22float2(p23);
    float4 L  = *(float4*)&out[idx];
    float4 cr = *(const float4*)&g_carry[c * NCH + b * Dd + d];
    L.x = fmaf(cr.x, P0.x, L.x);
    L.y = fmaf(cr.y, P0.y, L.y);
    L.z = fmaf(cr.z, P1.x, L.z);
    L.w = fmaf(cr.w, P1.y, L.w);
    *(float4*)&out[idx] = L;
}

// ---------------------------------------------------------------------------
extern "C" void kernel_launch(void* const* d_in, const int* in_sizes, int n_in,
                              void* d_out, int out_size)
{
    const float* x  = (const float*)d_in[0];
    const float* Wg = (const float*)d_in[1];
    const float* bg = (const float*)d_in[2];
    const float* Wv = (const float*)d_in[3];
    const float* bv = (const float*)d_in[4];
    const float* Wd = (const float*)d_in[5];
    const float* bd = (const float*)d_in[6];
    float* out = (float*)d_out;

    cudaFuncSetAttribute(gemm_mma_kernel,
                         cudaFuncAttributeMaxDynamicSharedMemorySize, SMEM_TOTAL);

    convert_x_kernel<<<Mtot * Dd / 4 / 256, 256>>>(x);
    convert_w_kernel<<<3 * Dd * Dd / 4 / 256, 256>>>(Wg, Wv, Wd);

    dim3 grid(Dd / TBN, Mtot / TBM, 3);   // (8, 128, 3)
    gemm_mma_kernel<<<grid, 128, SMEM_TOTAL>>>();

    scan_gate_kernel <<<(NCH / 2 * CHUNKS) / 256, 256>>>(out, bg, bv, bd);
    scan_carry_kernel<<<NCH / 256, 256>>>(out);
    scan_fix_kernel  <<<(Mtot * Dd / 4) / 256, 256>>>(out);
}